// round 2
// baseline (speedup 1.0000x reference)
#include <cuda_runtime.h>
#include <cstdint>

// Problem constants (capacity caps; actual sizes derived from in_sizes)
#define N_MAX 16384
#define SC    128   // shortcut
#define RED   32    // reduced
#define PWN   32    // pw narrow
#define PAIR  128
#define XDIM  96    // 2*RED + PWN

#define TPB 256
#define TS  128     // edges (or nodes) per tile

// scratch (allocation-free rule: static __device__ arrays)
__device__ float g_t[(size_t)N_MAX * RED];      // reduced node feats
__device__ float g_tmp[(size_t)N_MAX * PAIR];   // scatter-max accumulator

// ---------------------------------------------------------------------------
// Kernel 0: zero the scatter accumulator
// ---------------------------------------------------------------------------
__global__ void zero_tmp_kernel(int total) {
    int i = blockIdx.x * blockDim.x + threadIdx.x;
    if (i < total) g_tmp[i] = 0.0f;
}

// ---------------------------------------------------------------------------
// Kernel 1: t = relu(infeats @ W_rd + b_rd)   [N,128] -> [N,32]
// ---------------------------------------------------------------------------
__global__ __launch_bounds__(TPB, 1)
void reduce_kernel(const float* __restrict__ infeats,
                   const float* __restrict__ W_rd,
                   const float* __restrict__ b_rd, int N) {
    __shared__ float Ws[SC * RED];   // 16 KB
    __shared__ float rows[8 * SC];   // 4 KB
    int tid = threadIdx.x;
    for (int i = tid; i < SC * RED; i += TPB) Ws[i] = W_rd[i];
    int base = blockIdx.x * 8;
    for (int i = tid; i < 8 * SC; i += TPB) {
        int nl = i >> 7, k = i & 127;
        rows[i] = (base + nl < N) ? infeats[(size_t)(base + nl) * SC + k] : 0.0f;
    }
    __syncthreads();
    int nl = tid >> 5, r = tid & 31;
    float acc = b_rd[r];
#pragma unroll 8
    for (int i = 0; i < SC; i++) acc += rows[nl * SC + i] * Ws[i * RED + r];
    if (base + nl < N) g_t[(size_t)(base + nl) * RED + r] = fmaxf(acc, 0.0f);
}

// ---------------------------------------------------------------------------
// Kernel 2: fused per-edge MLP + scatter-max (persistent)
//   x  = [pw | t[c] | t[n]*(c!=n)]   (96)
//   h1 = relu(x @ W0 + b0)           (128)
//   h2 = relu(h1 @ W1 + b1)          (128)
//   tmp[c] = max(tmp[c], h2)         (atomicMax on int bits; values >= 0)
// 256 threads; tile = 128 edges x 128 outs; 8x8 register tile per thread.
// Inner loops step k by 4 with float4 broadcast loads (FFMA-dominated issue).
// ---------------------------------------------------------------------------
#define H1_LD 132
#define EDGE_SMEM_FLOATS (XDIM*PAIR + PAIR*PAIR + TS*H1_LD)
#define EDGE_SMEM_BYTES  (EDGE_SMEM_FLOATS*4 + 2*TS*4)

__global__ __launch_bounds__(TPB, 1)
void edge_kernel(const float* __restrict__ pw,
                 const int* __restrict__ c_idx,
                 const int* __restrict__ n_idx,
                 const float* __restrict__ W0, const float* __restrict__ b0,
                 const float* __restrict__ W1, const float* __restrict__ b1,
                 int E, int ntiles) {
    extern __shared__ float smem[];
    float* W0s = smem;                      // 96*128
    float* W1s = W0s + XDIM * PAIR;         // 128*128
    float* buf = W1s + PAIR * PAIR;         // X: [edge][96] / H1: [edge][132]
    int*   cs  = (int*)(buf + TS * H1_LD);  // 128
    int*   ns  = cs + TS;                   // 128

    int tid = threadIdx.x;
    for (int i = tid * 4; i < XDIM * PAIR; i += TPB * 4)
        *(float4*)&W0s[i] = *(const float4*)&W0[i];
    for (int i = tid * 4; i < PAIR * PAIR; i += TPB * 4)
        *(float4*)&W1s[i] = *(const float4*)&W1[i];

    const int tx = tid & 15, ty = tid >> 4;
    const int col0 = tx * 8, row0 = ty * 8;
    float bb0[8], bb1[8];
#pragma unroll
    for (int c = 0; c < 8; c++) { bb0[c] = b0[col0 + c]; bb1[c] = b1[col0 + c]; }

    for (int tile = blockIdx.x; tile < ntiles; tile += gridDim.x) {
        int base = tile * TS;
        int nvalid = min(TS, E - base);
        __syncthreads();  // guard buf/cs reuse across tiles
        if (tid < TS) {
            if (tid < nvalid) { cs[tid] = c_idx[base + tid]; ns[tid] = n_idx[base + tid]; }
            else              { cs[tid] = -1;                ns[tid] = -1; }
        }
        __syncthreads();

        // ---- gather X: buf[edge][0..95], row stride 96 ----
        for (int idx = tid; idx < TS * 8; idx += TPB) {
            int le = idx >> 3, k4 = (idx & 7) * 4;
            float4 v = make_float4(0.f, 0.f, 0.f, 0.f);
            if (le < nvalid) v = *(const float4*)&pw[(size_t)(base + le) * PWN + k4];
            *(float4*)&buf[le * XDIM + k4] = v;
        }
        for (int idx = tid; idx < TS * 8; idx += TPB) {
            int le = idx >> 3, k4 = (idx & 7) * 4;
            int c = cs[le], n = ns[le];
            float4 v = make_float4(0.f, 0.f, 0.f, 0.f);
            float4 w = make_float4(0.f, 0.f, 0.f, 0.f);
            if (c >= 0) {
                v = *(const float4*)&g_t[(size_t)c * RED + k4];
                if (n != c) w = *(const float4*)&g_t[(size_t)n * RED + k4];
            }
            *(float4*)&buf[le * XDIM + RED + k4]     = v;
            *(float4*)&buf[le * XDIM + 2 * RED + k4] = w;
        }
        __syncthreads();

        // ---- GEMM1: h1 = relu(X @ W0 + b0), k stepped by 4 ----
        float acc[8][8];
#pragma unroll
        for (int r = 0; r < 8; r++)
#pragma unroll
            for (int c = 0; c < 8; c++) acc[r][c] = 0.f;

        for (int k = 0; k < XDIM; k += 4) {
            float4 a[8];
#pragma unroll
            for (int r = 0; r < 8; r++)
                a[r] = *(float4*)&buf[(row0 + r) * XDIM + k];
#pragma unroll
            for (int kk = 0; kk < 4; kk++) {
                float4 w0 = *(float4*)&W0s[(k + kk) * PAIR + col0];
                float4 w1 = *(float4*)&W0s[(k + kk) * PAIR + col0 + 4];
                float b[8] = {w0.x, w0.y, w0.z, w0.w, w1.x, w1.y, w1.z, w1.w};
#pragma unroll
                for (int r = 0; r < 8; r++) {
                    float av = (kk == 0) ? a[r].x : (kk == 1) ? a[r].y
                             : (kk == 2) ? a[r].z : a[r].w;
#pragma unroll
                    for (int c = 0; c < 8; c++) acc[r][c] += av * b[c];
                }
            }
        }
        __syncthreads();  // X reads done; reuse buf for H1

        // write H1 = relu(acc + b0) as [edge][j], stride 132
#pragma unroll
        for (int r = 0; r < 8; r++) {
            float4 v0, v1;
            v0.x = fmaxf(acc[r][0] + bb0[0], 0.f);
            v0.y = fmaxf(acc[r][1] + bb0[1], 0.f);
            v0.z = fmaxf(acc[r][2] + bb0[2], 0.f);
            v0.w = fmaxf(acc[r][3] + bb0[3], 0.f);
            v1.x = fmaxf(acc[r][4] + bb0[4], 0.f);
            v1.y = fmaxf(acc[r][5] + bb0[5], 0.f);
            v1.z = fmaxf(acc[r][6] + bb0[6], 0.f);
            v1.w = fmaxf(acc[r][7] + bb0[7], 0.f);
            *(float4*)&buf[(row0 + r) * H1_LD + col0]     = v0;
            *(float4*)&buf[(row0 + r) * H1_LD + col0 + 4] = v1;
        }
        __syncthreads();

        // ---- GEMM2: h2pre = h1 @ W1, k stepped by 4 ----
#pragma unroll
        for (int r = 0; r < 8; r++)
#pragma unroll
            for (int c = 0; c < 8; c++) acc[r][c] = 0.f;

        for (int k = 0; k < PAIR; k += 4) {
            float4 a[8];
#pragma unroll
            for (int r = 0; r < 8; r++)
                a[r] = *(float4*)&buf[(row0 + r) * H1_LD + k];
#pragma unroll
            for (int kk = 0; kk < 4; kk++) {
                float4 w0 = *(float4*)&W1s[(k + kk) * PAIR + col0];
                float4 w1 = *(float4*)&W1s[(k + kk) * PAIR + col0 + 4];
                float b[8] = {w0.x, w0.y, w0.z, w0.w, w1.x, w1.y, w1.z, w1.w};
#pragma unroll
                for (int r = 0; r < 8; r++) {
                    float av = (kk == 0) ? a[r].x : (kk == 1) ? a[r].y
                             : (kk == 2) ? a[r].z : a[r].w;
#pragma unroll
                    for (int c = 0; c < 8; c++) acc[r][c] += av * b[c];
                }
            }
        }

        // ---- scatter-max: relu(acc + b1); values > 0 via int atomicMax ----
#pragma unroll
        for (int r = 0; r < 8; r++) {
            int c = cs[row0 + r];
            if (c >= 0) {
                float* dst = &g_tmp[(size_t)c * PAIR + col0];
#pragma unroll
                for (int cc = 0; cc < 8; cc++) {
                    float v = acc[r][cc] + bb1[cc];
                    if (v > 0.f) atomicMax((int*)&dst[cc], __float_as_int(v));
                }
            }
        }
    }
}

// ---------------------------------------------------------------------------
// Kernel 3: node MLP: out = relu(relu(relu(tmp@Wa+ba)@Wb+bb)@W2+b2 + infeats)
// ---------------------------------------------------------------------------
#define ACT_LD 132
#define NODE_SMEM_BYTES ((TS*ACT_LD + PAIR*PAIR) * 4)

__global__ __launch_bounds__(TPB, 1)
void node_kernel(const float* __restrict__ infeats,
                 const float* __restrict__ Wa, const float* __restrict__ ba,
                 const float* __restrict__ Wb, const float* __restrict__ bb_,
                 const float* __restrict__ W2, const float* __restrict__ b2,
                 float* __restrict__ out, int N) {
    extern __shared__ float smem[];
    float* acts = smem;               // 128*132
    float* Ws   = smem + TS * ACT_LD; // 128*128

    int tid = threadIdx.x;
    int base = blockIdx.x * TS;
    int nvalid = min(TS, N - base);

    for (int idx = tid; idx < TS * (PAIR / 4); idx += TPB) {
        int node = idx >> 5, k = (idx & 31) * 4;
        float4 v = make_float4(0.f, 0.f, 0.f, 0.f);
        if (node < nvalid) v = *(const float4*)&g_tmp[(size_t)(base + node) * PAIR + k];
        *(float4*)&acts[node * ACT_LD + k] = v;
    }

    const int tx = tid & 15, ty = tid >> 4;
    const int col0 = tx * 8, row0 = ty * 8;

    const float* Wp[3] = {Wa, Wb, W2};
    const float* bp[3] = {ba, bb_, b2};

    for (int layer = 0; layer < 3; layer++) {
        __syncthreads();  // acts writes visible; previous Ws reads done
        for (int i = tid * 4; i < PAIR * PAIR; i += TPB * 4)
            *(float4*)&Ws[i] = *(const float4*)&Wp[layer][i];
        __syncthreads();

        float acc[8][8];
#pragma unroll
        for (int r = 0; r < 8; r++)
#pragma unroll
            for (int c = 0; c < 8; c++) acc[r][c] = 0.f;

        for (int k = 0; k < PAIR; k += 4) {
            float4 a[8];
#pragma unroll
            for (int r = 0; r < 8; r++)
                a[r] = *(float4*)&acts[(row0 + r) * ACT_LD + k];
#pragma unroll
            for (int kk = 0; kk < 4; kk++) {
                float4 w0 = *(float4*)&Ws[(k + kk) * PAIR + col0];
                float4 w1 = *(float4*)&Ws[(k + kk) * PAIR + col0 + 4];
                float b[8] = {w0.x, w0.y, w0.z, w0.w, w1.x, w1.y, w1.z, w1.w};
#pragma unroll
                for (int r = 0; r < 8; r++) {
                    float av = (kk == 0) ? a[r].x : (kk == 1) ? a[r].y
                             : (kk == 2) ? a[r].z : a[r].w;
#pragma unroll
                    for (int c = 0; c < 8; c++) acc[r][c] += av * b[c];
                }
            }
        }
        __syncthreads();  // acts reads done

        float bias[8];
#pragma unroll
        for (int c = 0; c < 8; c++) bias[c] = bp[layer][col0 + c];

        if (layer < 2) {
#pragma unroll
            for (int r = 0; r < 8; r++) {
                float4 v0, v1;
                v0.x = fmaxf(acc[r][0] + bias[0], 0.f);
                v0.y = fmaxf(acc[r][1] + bias[1], 0.f);
                v0.z = fmaxf(acc[r][2] + bias[2], 0.f);
                v0.w = fmaxf(acc[r][3] + bias[3], 0.f);
                v1.x = fmaxf(acc[r][4] + bias[4], 0.f);
                v1.y = fmaxf(acc[r][5] + bias[5], 0.f);
                v1.z = fmaxf(acc[r][6] + bias[6], 0.f);
                v1.w = fmaxf(acc[r][7] + bias[7], 0.f);
                *(float4*)&acts[(row0 + r) * ACT_LD + col0]     = v0;
                *(float4*)&acts[(row0 + r) * ACT_LD + col0 + 4] = v1;
            }
        } else {
#pragma unroll
            for (int r = 0; r < 8; r++) {
                int node = row0 + r;
                if (node < nvalid) {
                    const float* inrow = &infeats[(size_t)(base + node) * SC + col0];
                    float* orow = &out[(size_t)(base + node) * SC + col0];
                    float4 i0 = *(const float4*)&inrow[0];
                    float4 i1 = *(const float4*)&inrow[4];
                    float4 v0, v1;
                    v0.x = fmaxf(acc[r][0] + bias[0] + i0.x, 0.f);
                    v0.y = fmaxf(acc[r][1] + bias[1] + i0.y, 0.f);
                    v0.z = fmaxf(acc[r][2] + bias[2] + i0.z, 0.f);
                    v0.w = fmaxf(acc[r][3] + bias[3] + i0.w, 0.f);
                    v1.x = fmaxf(acc[r][4] + bias[4] + i1.x, 0.f);
                    v1.y = fmaxf(acc[r][5] + bias[5] + i1.y, 0.f);
                    v1.z = fmaxf(acc[r][6] + bias[6] + i1.z, 0.f);
                    v1.w = fmaxf(acc[r][7] + bias[7] + i1.w, 0.f);
                    *(float4*)&orow[0] = v0;
                    *(float4*)&orow[4] = v1;
                }
            }
        }
    }
}

// ---------------------------------------------------------------------------
extern "C" void kernel_launch(void* const* d_in, const int* in_sizes, int n_in,
                              void* d_out, int out_size) {
    const float* infeats = (const float*)d_in[0];
    const float* pw      = (const float*)d_in[1];
    const int*   c_idxs  = (const int*)d_in[2];
    const int*   n_idxs  = (const int*)d_in[3];
    // d_in[4] = dets_num (== N, derived from sizes instead)
    const float* W_rd  = (const float*)d_in[5];
    const float* b_rd  = (const float*)d_in[6];
    const float* W_pw0 = (const float*)d_in[7];
    const float* b_pw0 = (const float*)d_in[8];
    const float* W_pw1 = (const float*)d_in[9];
    const float* b_pw1 = (const float*)d_in[10];
    const float* W_f1a = (const float*)d_in[11];
    const float* b_f1a = (const float*)d_in[12];
    const float* W_f1b = (const float*)d_in[13];
    const float* b_f1b = (const float*)d_in[14];
    const float* W_f2  = (const float*)d_in[15];
    const float* b_f2  = (const float*)d_in[16];
    float* out = (float*)d_out;

    int N = in_sizes[0] / SC;
    int E = in_sizes[1] / PWN;

    cudaFuncSetAttribute(edge_kernel, cudaFuncAttributeMaxDynamicSharedMemorySize,
                         EDGE_SMEM_BYTES);
    cudaFuncSetAttribute(node_kernel, cudaFuncAttributeMaxDynamicSharedMemorySize,
                         NODE_SMEM_BYTES);

    // 0: zero accumulator
    int tot = N * PAIR;
    zero_tmp_kernel<<<(tot + 255) / 256, 256>>>(tot);

    // 1: reduce_dim
    reduce_kernel<<<(N + 7) / 8, TPB>>>(infeats, W_rd, b_rd, N);

    // 2: fused edge MLP + scatter-max (persistent over edge tiles)
    int ntiles = (E + TS - 1) / TS;
    int grid = ntiles < 148 ? ntiles : 148;
    edge_kernel<<<grid, TPB, EDGE_SMEM_BYTES>>>(pw, c_idxs, n_idxs,
                                                W_pw0, b_pw0, W_pw1, b_pw1,
                                                E, ntiles);

    // 3: node MLP + residual
    node_kernel<<<(N + TS - 1) / TS, TPB, NODE_SMEM_BYTES>>>(
        infeats, W_f1a, b_f1a, W_f1b, b_f1b, W_f2, b_f2, out, N);
}

// round 5
// speedup vs baseline: 1.6108x; 1.6108x over previous
#include <cuda_runtime.h>
#include <cuda_bf16.h>
#include <cstdint>

#define N_MAX 16384
#define SC    128
#define RED   32
#define PWN   32
#define PAIR  128
#define XDIM  96

#define TPB 256
#define TS  128
#define PX  136     // bf16 element pitch of activation/weight planes

__device__ float g_t[(size_t)N_MAX * RED];
__device__ float g_tmp[(size_t)N_MAX * PAIR];

// ---------------------------------------------------------------------------
// helpers
// ---------------------------------------------------------------------------
__device__ __forceinline__ uint32_t smem_u32(const void* p) {
    uint32_t a;
    asm("{ .reg .u64 t; cvta.to.shared.u64 t, %1; cvt.u32.u64 %0, t; }" : "=r"(a) : "l"(p));
    return a;
}
__device__ __forceinline__ void ldsm_x4(uint32_t& r0, uint32_t& r1, uint32_t& r2,
                                        uint32_t& r3, uint32_t addr) {
    asm volatile("ldmatrix.sync.aligned.m8n8.x4.shared.b16 {%0,%1,%2,%3}, [%4];"
                 : "=r"(r0), "=r"(r1), "=r"(r2), "=r"(r3) : "r"(addr));
}
__device__ __forceinline__ void mma_bf16(float* c, const uint32_t* a, const uint32_t* b) {
    asm volatile(
        "mma.sync.aligned.m16n8k16.row.col.f32.bf16.bf16.f32 "
        "{%0,%1,%2,%3}, {%4,%5,%6,%7}, {%8,%9}, {%0,%1,%2,%3};"
        : "+f"(c[0]), "+f"(c[1]), "+f"(c[2]), "+f"(c[3])
        : "r"(a[0]), "r"(a[1]), "r"(a[2]), "r"(a[3]), "r"(b[0]), "r"(b[1]));
}
__device__ __forceinline__ void split_bf16(float x, uint16_t& h, uint16_t& l) {
    __nv_bfloat16 hb = __float2bfloat16_rn(x);
    float hf = __bfloat162float(hb);
    __nv_bfloat16 lb = __float2bfloat16_rn(x - hf);
    h = *(uint16_t*)&hb; l = *(uint16_t*)&lb;
}
__device__ __forceinline__ uint32_t pack2(uint16_t a, uint16_t b) {
    return (uint32_t)a | ((uint32_t)b << 16);
}

// ---------------------------------------------------------------------------
__global__ void zero_tmp_kernel(int total) {
    int i = blockIdx.x * blockDim.x + threadIdx.x;
    if (i < total) g_tmp[i] = 0.0f;
}

// ---------------------------------------------------------------------------
// Kernel 1: t = relu(infeats @ W_rd + b_rd)
// ---------------------------------------------------------------------------
__global__ __launch_bounds__(TPB, 1)
void reduce_kernel(const float* __restrict__ infeats,
                   const float* __restrict__ W_rd,
                   const float* __restrict__ b_rd, int N) {
    __shared__ float Ws[SC * RED];
    __shared__ float rows[8 * SC];
    int tid = threadIdx.x;
    for (int i = tid; i < SC * RED; i += TPB) Ws[i] = W_rd[i];
    int base = blockIdx.x * 8;
    for (int i = tid; i < 8 * SC; i += TPB) {
        int nl = i >> 7, k = i & 127;
        rows[i] = (base + nl < N) ? infeats[(size_t)(base + nl) * SC + k] : 0.0f;
    }
    __syncthreads();
    int nl = tid >> 5, r = tid & 31;
    float acc = b_rd[r];
#pragma unroll 8
    for (int i = 0; i < SC; i++) acc += rows[nl * SC + i] * Ws[i * RED + r];
    if (base + nl < N) g_t[(size_t)(base + nl) * RED + r] = fmaxf(acc, 0.0f);
}

// ---------------------------------------------------------------------------
// Kernel 2: fused edge MLP via mma.sync bf16 (hi/lo 3-pass) + scatter-max
// SMEM byte offsets (all 16B aligned); planes are [128 rows][PX bf16]
// ---------------------------------------------------------------------------
#define PLANE_B (128 * PX * 2)   // 34816
#define OFF_XH  0
#define OFF_XL  (OFF_XH + PLANE_B)
#define OFF_W0H (OFF_XL + PLANE_B)
#define OFF_W0L (OFF_W0H + PLANE_B)
#define OFF_W1H (OFF_W0L + PLANE_B)
#define OFF_W1L (OFF_W1H + PLANE_B)
#define OFF_CS  (OFF_W1L + PLANE_B)
#define OFF_NS  (OFF_CS + 512)
#define OFF_B0  (OFF_NS + 512)
#define OFF_B1  (OFF_B0 + 512)
#define EDGE_SMEM_BYTES (OFF_B1 + 512)

// One GEMM over the 128x128 tile: A = act planes, B = weight planes (as W^T
// [j][k]). Per warp: 32 rows x 64 cols; KS k-steps of 16.
template <int KS>
__device__ __forceinline__ void gemm_tile(uint32_t xh, uint32_t xl,
                                          uint32_t wh, uint32_t wl,
                                          int wrow, int wcol, int lid,
                                          float acc[2][8][4]) {
#pragma unroll
    for (int m = 0; m < 2; m++)
#pragma unroll
        for (int n = 0; n < 8; n++)
#pragma unroll
            for (int i = 0; i < 4; i++) acc[m][n][i] = 0.f;

    // ldmatrix lane address components
    const int a_row = (lid & 7) + ((lid >> 3) & 1) * 8;   // within m16
    const int a_col = ((lid >> 4) & 1) * 8;               // k half
    const int b_row = (lid & 7) + ((lid >> 4) & 1) * 8;   // within n16
    const int b_col = ((lid >> 3) & 1) * 8;               // k half

#pragma unroll 2
    for (int ks = 0; ks < KS; ks++) {
        const int k0 = ks * 16;
        uint32_t Ah[2][4], Al[2][4];
#pragma unroll
        for (int m = 0; m < 2; m++) {
            uint32_t off = (uint32_t)((wrow + m * 16 + a_row) * PX + k0 + a_col) * 2;
            ldsm_x4(Ah[m][0], Ah[m][1], Ah[m][2], Ah[m][3], xh + off);
            ldsm_x4(Al[m][0], Al[m][1], Al[m][2], Al[m][3], xl + off);
        }
        uint32_t Bh[8][2], Bl[8][2];
#pragma unroll
        for (int nn = 0; nn < 4; nn++) {
            uint32_t off = (uint32_t)((wcol + nn * 16 + b_row) * PX + k0 + b_col) * 2;
            uint32_t r0, r1, r2, r3;
            ldsm_x4(r0, r1, r2, r3, wh + off);
            Bh[nn * 2][0] = r0; Bh[nn * 2][1] = r1;
            Bh[nn * 2 + 1][0] = r2; Bh[nn * 2 + 1][1] = r3;
            ldsm_x4(r0, r1, r2, r3, wl + off);
            Bl[nn * 2][0] = r0; Bl[nn * 2][1] = r1;
            Bl[nn * 2 + 1][0] = r2; Bl[nn * 2 + 1][1] = r3;
        }
#pragma unroll
        for (int m = 0; m < 2; m++)
#pragma unroll
            for (int n = 0; n < 8; n++) {
                mma_bf16(acc[m][n], Ah[m], Bh[n]);
                mma_bf16(acc[m][n], Ah[m], Bl[n]);
                mma_bf16(acc[m][n], Al[m], Bh[n]);
            }
    }
}

__global__ __launch_bounds__(TPB, 1)
void edge_kernel(const float* __restrict__ pw,
                 const int* __restrict__ c_idx,
                 const int* __restrict__ n_idx,
                 const float* __restrict__ W0, const float* __restrict__ b0,
                 const float* __restrict__ W1, const float* __restrict__ b1,
                 int E, int ntiles) {
    extern __shared__ char smem[];
    const uint32_t sb = smem_u32(smem);
    const uint32_t xh = sb + OFF_XH, xl = sb + OFF_XL;
    const uint32_t w0h = sb + OFF_W0H, w0l = sb + OFF_W0L;
    const uint32_t w1h = sb + OFF_W1H, w1l = sb + OFF_W1L;
    int*   cs  = (int*)(smem + OFF_CS);
    int*   ns  = (int*)(smem + OFF_NS);
    float* b0s = (float*)(smem + OFF_B0);
    float* b1s = (float*)(smem + OFF_B1);

    const int tid = threadIdx.x;
    const int wid = tid >> 5, lid = tid & 31;
    const int wrow = (wid & 3) * 32, wcol = (wid >> 2) * 64;
    const int g = lid >> 2, t = lid & 3;

    // ---- weights: transpose to [j][k], split hi/lo ----
    for (int idx = tid; idx < XDIM * PAIR; idx += TPB) {
        int k = idx >> 7, j = idx & 127;   // W0[k][j]
        uint16_t h, l; split_bf16(W0[idx], h, l);
        uint32_t o = (uint32_t)(j * PX + k) * 2;
        *(uint16_t*)(smem + OFF_W0H + o) = h;
        *(uint16_t*)(smem + OFF_W0L + o) = l;
    }
    for (int idx = tid; idx < PAIR * PAIR; idx += TPB) {
        int k = idx >> 7, j = idx & 127;
        uint16_t h, l; split_bf16(W1[idx], h, l);
        uint32_t o = (uint32_t)(j * PX + k) * 2;
        *(uint16_t*)(smem + OFF_W1H + o) = h;
        *(uint16_t*)(smem + OFF_W1L + o) = l;
    }
    if (tid < PAIR) { b0s[tid] = b0[tid]; b1s[tid] = b1[tid]; }

    for (int tile = blockIdx.x; tile < ntiles; tile += gridDim.x) {
        int base = tile * TS;
        int nvalid = min(TS, E - base);
        __syncthreads();   // previous tile fully consumed
        if (tid < TS) {
            if (tid < nvalid) { cs[tid] = c_idx[base + tid]; ns[tid] = n_idx[base + tid]; }
            else              { cs[tid] = -1;                ns[tid] = -1; }
        }
        __syncthreads();

        // ---- gather X rows (edges) cols 0..95 into hi/lo planes ----
        for (int idx = tid; idx < TS * 24; idx += TPB) {
            int r = idx / 24, gg = idx - r * 24;
            float4 v = make_float4(0.f, 0.f, 0.f, 0.f);
            if (r < nvalid) {
                if (gg < 8) {
                    v = *(const float4*)&pw[(size_t)(base + r) * PWN + gg * 4];
                } else {
                    int c = cs[r], n = ns[r];
                    if (gg < 16) v = *(const float4*)&g_t[(size_t)c * RED + (gg - 8) * 4];
                    else if (n != c) v = *(const float4*)&g_t[(size_t)n * RED + (gg - 16) * 4];
                }
            }
            uint16_t h0,l0,h1,l1,h2,l2,h3,l3;
            split_bf16(v.x,h0,l0); split_bf16(v.y,h1,l1);
            split_bf16(v.z,h2,l2); split_bf16(v.w,h3,l3);
            uint32_t o = (uint32_t)(r * PX + gg * 4) * 2;
            *(uint2*)(smem + OFF_XH + o) = make_uint2(pack2(h0,h1), pack2(h2,h3));
            *(uint2*)(smem + OFF_XL + o) = make_uint2(pack2(l0,l1), pack2(l2,l3));
        }
        __syncthreads();

        // ---- GEMM1: K=96 (6 k-steps) ----
        float acc[2][8][4];
        gemm_tile<6>(xh, xl, w0h, w0l, wrow, wcol, lid, acc);
        __syncthreads();   // all X reads done before overwrite

        // ---- epilogue 1: relu(acc+b0) -> split -> H1 planes ----
#pragma unroll
        for (int m = 0; m < 2; m++) {
            int r0 = wrow + m * 16 + g;
#pragma unroll
            for (int n = 0; n < 8; n++) {
                int col = wcol + n * 8 + t * 2;
                float bx = b0s[col], by = b0s[col + 1];
                float v0 = fmaxf(acc[m][n][0] + bx, 0.f);
                float v1 = fmaxf(acc[m][n][1] + by, 0.f);
                float v2 = fmaxf(acc[m][n][2] + bx, 0.f);
                float v3 = fmaxf(acc[m][n][3] + by, 0.f);
                uint16_t h0,l0,h1,l1,h2,l2,h3,l3;
                split_bf16(v0,h0,l0); split_bf16(v1,h1,l1);
                split_bf16(v2,h2,l2); split_bf16(v3,h3,l3);
                uint32_t o0 = (uint32_t)(r0 * PX + col) * 2;
                uint32_t o1 = (uint32_t)((r0 + 8) * PX + col) * 2;
                *(uint32_t*)(smem + OFF_XH + o0) = pack2(h0, h1);
                *(uint32_t*)(smem + OFF_XL + o0) = pack2(l0, l1);
                *(uint32_t*)(smem + OFF_XH + o1) = pack2(h2, h3);
                *(uint32_t*)(smem + OFF_XL + o1) = pack2(l2, l3);
            }
        }
        __syncthreads();

        // ---- GEMM2: K=128 (8 k-steps) ----
        gemm_tile<8>(xh, xl, w1h, w1l, wrow, wcol, lid, acc);

        // ---- epilogue 2: relu(acc+b1) -> scatter atomicMax ----
#pragma unroll
        for (int m = 0; m < 2; m++) {
            int r0 = wrow + m * 16 + g;
            int e0 = cs[r0], e1 = cs[r0 + 8];
#pragma unroll
            for (int n = 0; n < 8; n++) {
                int col = wcol + n * 8 + t * 2;
                float bx = b1s[col], by = b1s[col + 1];
                if (e0 >= 0) {
                    float v0 = acc[m][n][0] + bx;
                    float v1 = acc[m][n][1] + by;
                    float* dst = &g_tmp[(size_t)e0 * PAIR + col];
                    if (v0 > 0.f) atomicMax((int*)&dst[0], __float_as_int(v0));
                    if (v1 > 0.f) atomicMax((int*)&dst[1], __float_as_int(v1));
                }
                if (e1 >= 0) {
                    float v2 = acc[m][n][2] + bx;
                    float v3 = acc[m][n][3] + by;
                    float* dst = &g_tmp[(size_t)e1 * PAIR + col];
                    if (v2 > 0.f) atomicMax((int*)&dst[0], __float_as_int(v2));
                    if (v3 > 0.f) atomicMax((int*)&dst[1], __float_as_int(v3));
                }
            }
        }
    }
}

// ---------------------------------------------------------------------------
// Kernel 3: node MLP (512 threads, 4x8 thread tiles)
// ---------------------------------------------------------------------------
#define NTPB 512
#define ACT_LD 132
#define NODE_SMEM_BYTES ((TS*ACT_LD + PAIR*PAIR) * 4)

__global__ __launch_bounds__(NTPB, 1)
void node_kernel(const float* __restrict__ infeats,
                 const float* __restrict__ Wa, const float* __restrict__ ba,
                 const float* __restrict__ Wb, const float* __restrict__ bb_,
                 const float* __restrict__ W2, const float* __restrict__ b2,
                 float* __restrict__ out, int N) {
    extern __shared__ float smemf[];
    float* acts = smemf;
    float* Ws   = smemf + TS * ACT_LD;

    int tid = threadIdx.x;
    int base = blockIdx.x * TS;
    int nvalid = min(TS, N - base);

    for (int idx = tid; idx < TS * (PAIR / 4); idx += NTPB) {
        int node = idx >> 5, k = (idx & 31) * 4;
        float4 v = make_float4(0.f, 0.f, 0.f, 0.f);
        if (node < nvalid) v = *(const float4*)&g_tmp[(size_t)(base + node) * PAIR + k];
        *(float4*)&acts[node * ACT_LD + k] = v;
    }

    const int tx = tid & 15, ty = tid >> 4;
    const int col0 = tx * 8, row0 = ty * 4;

    const float* Wp[3] = {Wa, Wb, W2};
    const float* bp[3] = {ba, bb_, b2};

    for (int layer = 0; layer < 3; layer++) {
        __syncthreads();
        for (int i = tid * 4; i < PAIR * PAIR; i += NTPB * 4)
            *(float4*)&Ws[i] = *(const float4*)&Wp[layer][i];
        __syncthreads();

        float acc[4][8];
#pragma unroll
        for (int r = 0; r < 4; r++)
#pragma unroll
            for (int c = 0; c < 8; c++) acc[r][c] = 0.f;

        for (int k = 0; k < PAIR; k += 4) {
            float4 a[4];
#pragma unroll
            for (int r = 0; r < 4; r++)
                a[r] = *(float4*)&acts[(row0 + r) * ACT_LD + k];
#pragma unroll
            for (int kk = 0; kk < 4; kk++) {
                float4 w0 = *(float4*)&Ws[(k + kk) * PAIR + col0];
                float4 w1 = *(float4*)&Ws[(k + kk) * PAIR + col0 + 4];
                float b[8] = {w0.x, w0.y, w0.z, w0.w, w1.x, w1.y, w1.z, w1.w};
#pragma unroll
                for (int r = 0; r < 4; r++) {
                    float av = (kk == 0) ? a[r].x : (kk == 1) ? a[r].y
                             : (kk == 2) ? a[r].z : a[r].w;
#pragma unroll
                    for (int c = 0; c < 8; c++) acc[r][c] += av * b[c];
                }
            }
        }
        __syncthreads();

        float bias[8];
#pragma unroll
        for (int c = 0; c < 8; c++) bias[c] = bp[layer][col0 + c];

        if (layer < 2) {
#pragma unroll
            for (int r = 0; r < 4; r++) {
                float4 v0, v1;
                v0.x = fmaxf(acc[r][0] + bias[0], 0.f);
                v0.y = fmaxf(acc[r][1] + bias[1], 0.f);
                v0.z = fmaxf(acc[r][2] + bias[2], 0.f);
                v0.w = fmaxf(acc[r][3] + bias[3], 0.f);
                v1.x = fmaxf(acc[r][4] + bias[4], 0.f);
                v1.y = fmaxf(acc[r][5] + bias[5], 0.f);
                v1.z = fmaxf(acc[r][6] + bias[6], 0.f);
                v1.w = fmaxf(acc[r][7] + bias[7], 0.f);
                *(float4*)&acts[(row0 + r) * ACT_LD + col0]     = v0;
                *(float4*)&acts[(row0 + r) * ACT_LD + col0 + 4] = v1;
            }
        } else {
#pragma unroll
            for (int r = 0; r < 4; r++) {
                int node = row0 + r;
                if (node < nvalid) {
                    const float* inrow = &infeats[(size_t)(base + node) * SC + col0];
                    float* orow = &out[(size_t)(base + node) * SC + col0];
                    float4 i0 = *(const float4*)&inrow[0];
                    float4 i1 = *(const float4*)&inrow[4];
                    float4 v0, v1;
                    v0.x = fmaxf(acc[r][0] + bias[0] + i0.x, 0.f);
                    v0.y = fmaxf(acc[r][1] + bias[1] + i0.y, 0.f);
                    v0.z = fmaxf(acc[r][2] + bias[2] + i0.z, 0.f);
                    v0.w = fmaxf(acc[r][3] + bias[3] + i0.w, 0.f);
                    v1.x = fmaxf(acc[r][4] + bias[4] + i1.x, 0.f);
                    v1.y = fmaxf(acc[r][5] + bias[5] + i1.y, 0.f);
                    v1.z = fmaxf(acc[r][6] + bias[6] + i1.z, 0.f);
                    v1.w = fmaxf(acc[r][7] + bias[7] + i1.w, 0.f);
                    *(float4*)&orow[0] = v0;
                    *(float4*)&orow[4] = v1;
                }
            }
        }
    }
}

// ---------------------------------------------------------------------------
extern "C" void kernel_launch(void* const* d_in, const int* in_sizes, int n_in,
                              void* d_out, int out_size) {
    const float* infeats = (const float*)d_in[0];
    const float* pw      = (const float*)d_in[1];
    const int*   c_idxs  = (const int*)d_in[2];
    const int*   n_idxs  = (const int*)d_in[3];
    const float* W_rd  = (const float*)d_in[5];
    const float* b_rd  = (const float*)d_in[6];
    const float* W_pw0 = (const float*)d_in[7];
    const float* b_pw0 = (const float*)d_in[8];
    const float* W_pw1 = (const float*)d_in[9];
    const float* b_pw1 = (const float*)d_in[10];
    const float* W_f1a = (const float*)d_in[11];
    const float* b_f1a = (const float*)d_in[12];
    const float* W_f1b = (const float*)d_in[13];
    const float* b_f1b = (const float*)d_in[14];
    const float* W_f2  = (const float*)d_in[15];
    const float* b_f2  = (const float*)d_in[16];
    float* out = (float*)d_out;

    int N = in_sizes[0] / SC;
    int E = in_sizes[1] / PWN;

    cudaFuncSetAttribute(edge_kernel, cudaFuncAttributeMaxDynamicSharedMemorySize,
                         EDGE_SMEM_BYTES);
    cudaFuncSetAttribute(node_kernel, cudaFuncAttributeMaxDynamicSharedMemorySize,
                         NODE_SMEM_BYTES);

    int tot = N * PAIR;
    zero_tmp_kernel<<<(tot + 255) / 256, 256>>>(tot);

    reduce_kernel<<<(N + 7) / 8, TPB>>>(infeats, W_rd, b_rd, N);

    int ntiles = (E + TS - 1) / TS;
    int grid = ntiles < 148 ? ntiles : 148;
    edge_kernel<<<grid, TPB, EDGE_SMEM_BYTES>>>(pw, c_idxs, n_idxs,
                                                W_pw0, b_pw0, W_pw1, b_pw1,
                                                E, ntiles);

    node_kernel<<<(N + TS - 1) / TS, NTPB, NODE_SMEM_BYTES>>>(
        infeats, W_f1a, b_f1a, W_f1b, b_f1b, W_f2, b_f2, out, N);
}

// round 8
// speedup vs baseline: 1.9527x; 1.2122x over previous
#include <cuda_runtime.h>
#include <cuda_bf16.h>
#include <cstdint>

// Fused edge-MLP graph network, bf16 hi/lo 3-pass tensor-core path. v7.
#define N_MAX 16384
#define SC    128
#define RED   32
#define PWN   32
#define PAIR  128
#define XDIM  96

#define TPB  256
#define ETPB 512
#define TS   128
#define PX   136     // bf16 element pitch of activation/weight planes

__device__ float g_t[(size_t)N_MAX * RED];
__device__ float g_tmp[(size_t)N_MAX * PAIR];

// ---------------------------------------------------------------------------
// helpers
// ---------------------------------------------------------------------------
__device__ __forceinline__ uint32_t smem_addr32(const void* p) {
    uint32_t a;
    asm("{ .reg .u64 t; cvta.to.shared.u64 t, %1; cvt.u32.u64 %0, t; }" : "=r"(a) : "l"(p));
    return a;
}
__device__ __forceinline__ void ldsm4(uint32_t& r0, uint32_t& r1, uint32_t& r2,
                                      uint32_t& r3, uint32_t addr) {
    asm volatile("ldmatrix.sync.aligned.m8n8.x4.shared.b16 {%0,%1,%2,%3}, [%4];"
                 : "=r"(r0), "=r"(r1), "=r"(r2), "=r"(r3) : "r"(addr));
}
__device__ __forceinline__ void hmma(float* c, const uint32_t* a, const uint32_t* b) {
    asm volatile(
        "mma.sync.aligned.m16n8k16.row.col.f32.bf16.bf16.f32 "
        "{%0,%1,%2,%3}, {%4,%5,%6,%7}, {%8,%9}, {%0,%1,%2,%3};"
        : "+f"(c[0]), "+f"(c[1]), "+f"(c[2]), "+f"(c[3])
        : "r"(a[0]), "r"(a[1]), "r"(a[2]), "r"(a[3]), "r"(b[0]), "r"(b[1]));
}
__device__ __forceinline__ void hilo(float x, uint16_t& h, uint16_t& l) {
    __nv_bfloat16 hb = __float2bfloat16_rn(x);
    __nv_bfloat16 lb = __float2bfloat16_rn(x - __bfloat162float(hb));
    h = *(uint16_t*)&hb;
    l = *(uint16_t*)&lb;
}
__device__ __forceinline__ uint32_t pk2(uint16_t a, uint16_t b) {
    return (uint32_t)a | ((uint32_t)b << 16);
}

// ---------------------------------------------------------------------------
__global__ void clear_accum_kernel(int total) {
    int i = blockIdx.x * blockDim.x + threadIdx.x;
    if (i < total) g_tmp[i] = 0.0f;
}

// ---------------------------------------------------------------------------
// Kernel 1: t = relu(infeats @ W_rd + b_rd)
// ---------------------------------------------------------------------------
__global__ __launch_bounds__(TPB, 1)
void reduce_kernel(const float* __restrict__ infeats,
                   const float* __restrict__ W_rd,
                   const float* __restrict__ b_rd, int N) {
    __shared__ float Ws[SC * RED];
    __shared__ float rows[8 * SC];
    const int tid = threadIdx.x;
    const int base = blockIdx.x * 8;
    for (int i = tid; i < SC * RED; i += TPB) Ws[i] = W_rd[i];
    for (int i = tid; i < 8 * SC; i += TPB) {
        int nl = i >> 7, k = i & 127;
        rows[i] = (base + nl < N) ? infeats[(size_t)(base + nl) * SC + k] : 0.0f;
    }
    __syncthreads();
    const int nl = tid >> 5, r = tid & 31;
    float acc = b_rd[r];
#pragma unroll 8
    for (int i = 0; i < SC; i++) acc += rows[nl * SC + i] * Ws[i * RED + r];
    if (base + nl < N) g_t[(size_t)(base + nl) * RED + r] = fmaxf(acc, 0.0f);
}

// ---------------------------------------------------------------------------
// Kernel 2: fused edge MLP (mma.sync bf16 hi/lo 3-pass) + scatter-max.
// 512 threads / 16 warps; warp strip = 32 rows x 32 cols of the 128x128 tile.
// ---------------------------------------------------------------------------
#define PLANE_B (128 * PX * 2)   // 34816 bytes per bf16 plane
#define OFF_XH  0
#define OFF_XL  (OFF_XH + PLANE_B)
#define OFF_W0H (OFF_XL + PLANE_B)
#define OFF_W0L (OFF_W0H + PLANE_B)
#define OFF_W1H (OFF_W0L + PLANE_B)
#define OFF_W1L (OFF_W1H + PLANE_B)
#define OFF_CS  (OFF_W1L + PLANE_B)
#define OFF_NS  (OFF_CS + 512)
#define OFF_B0  (OFF_NS + 512)
#define OFF_B1  (OFF_B0 + 512)
#define EDGE_SMEM_BYTES (OFF_B1 + 512)

// lane offsets for ldmatrix, precomputed by caller
struct LaneMap { int a_row, a_col, b_row, b_col; };

template <int KS>
__device__ __forceinline__ void gemm_strip(uint32_t xh, uint32_t xl,
                                           uint32_t wh, uint32_t wl,
                                           int wrow, int wcol, LaneMap lm,
                                           float acc[2][4][4]) {
#pragma unroll
    for (int m = 0; m < 2; m++)
#pragma unroll
        for (int n = 0; n < 4; n++)
#pragma unroll
            for (int i = 0; i < 4; i++) acc[m][n][i] = 0.f;

#pragma unroll 2
    for (int ks = 0; ks < KS; ks++) {
        const int k0 = ks * 16;
        uint32_t Ah[2][4], Al[2][4];
#pragma unroll
        for (int m = 0; m < 2; m++) {
            uint32_t off = (uint32_t)((wrow + m * 16 + lm.a_row) * PX + k0 + lm.a_col) * 2;
            ldsm4(Ah[m][0], Ah[m][1], Ah[m][2], Ah[m][3], xh + off);
            ldsm4(Al[m][0], Al[m][1], Al[m][2], Al[m][3], xl + off);
        }
        uint32_t Bh[4][2], Bl[4][2];
#pragma unroll
        for (int nn = 0; nn < 2; nn++) {
            uint32_t off = (uint32_t)((wcol + nn * 16 + lm.b_row) * PX + k0 + lm.b_col) * 2;
            uint32_t r0, r1, r2, r3;
            ldsm4(r0, r1, r2, r3, wh + off);
            Bh[nn * 2][0] = r0;     Bh[nn * 2][1] = r1;
            Bh[nn * 2 + 1][0] = r2; Bh[nn * 2 + 1][1] = r3;
            ldsm4(r0, r1, r2, r3, wl + off);
            Bl[nn * 2][0] = r0;     Bl[nn * 2][1] = r1;
            Bl[nn * 2 + 1][0] = r2; Bl[nn * 2 + 1][1] = r3;
        }
#pragma unroll
        for (int m = 0; m < 2; m++)
#pragma unroll
            for (int n = 0; n < 4; n++) {
                hmma(acc[m][n], Ah[m], Bh[n]);
                hmma(acc[m][n], Ah[m], Bl[n]);
                hmma(acc[m][n], Al[m], Bh[n]);
            }
    }
}

__global__ __launch_bounds__(ETPB, 1)
void edge_kernel(const float* __restrict__ pw,
                 const int* __restrict__ c_idx,
                 const int* __restrict__ n_idx,
                 const float* __restrict__ W0, const float* __restrict__ b0,
                 const float* __restrict__ W1, const float* __restrict__ b1,
                 int E, int ntiles) {
    extern __shared__ char smem[];
    const uint32_t sb  = smem_addr32(smem);
    const uint32_t xh  = sb + OFF_XH,  xl  = sb + OFF_XL;
    const uint32_t w0h = sb + OFF_W0H, w0l = sb + OFF_W0L;
    const uint32_t w1h = sb + OFF_W1H, w1l = sb + OFF_W1L;
    int*   cs  = (int*)(smem + OFF_CS);
    int*   ns  = (int*)(smem + OFF_NS);
    float* b0s = (float*)(smem + OFF_B0);
    float* b1s = (float*)(smem + OFF_B1);

    const int tid = threadIdx.x;
    const int wid = tid >> 5, lid = tid & 31;
    const int wrow = (wid & 3) * 32;
    const int wcol = (wid >> 2) * 32;
    const int g = lid >> 2, t = lid & 3;

    LaneMap lm;
    lm.a_row = (lid & 7) + ((lid >> 3) & 1) * 8;
    lm.a_col = ((lid >> 4) & 1) * 8;
    lm.b_row = (lid & 7) + ((lid >> 4) & 1) * 8;
    lm.b_col = ((lid >> 3) & 1) * 8;

    // weights: transpose W[k][j] -> planes[j][k], hi/lo split
    for (int idx = tid; idx < XDIM * PAIR; idx += ETPB) {
        int k = idx >> 7, j = idx & 127;
        uint16_t h, l; hilo(W0[idx], h, l);
        uint32_t o = (uint32_t)(j * PX + k) * 2;
        *(uint16_t*)(smem + OFF_W0H + o) = h;
        *(uint16_t*)(smem + OFF_W0L + o) = l;
    }
    for (int idx = tid; idx < PAIR * PAIR; idx += ETPB) {
        int k = idx >> 7, j = idx & 127;
        uint16_t h, l; hilo(W1[idx], h, l);
        uint32_t o = (uint32_t)(j * PX + k) * 2;
        *(uint16_t*)(smem + OFF_W1H + o) = h;
        *(uint16_t*)(smem + OFF_W1L + o) = l;
    }
    if (tid < PAIR) { b0s[tid] = b0[tid]; b1s[tid] = b1[tid]; }

    for (int tile = blockIdx.x; tile < ntiles; tile += gridDim.x) {
        const int base = tile * TS;
        const int nvalid = min(TS, E - base);
        __syncthreads();   // previous tile fully consumed (cs/planes reusable)
        if (tid < TS) {
            bool ok = tid < nvalid;
            cs[tid] = ok ? c_idx[base + tid] : -1;
            ns[tid] = ok ? n_idx[base + tid] : -1;
        }
        __syncthreads();

        // gather X rows (edges), cols 0..95, into hi/lo planes
        for (int idx = tid; idx < TS * 24; idx += ETPB) {
            int r = idx / 24, gg = idx - r * 24;
            float4 v = make_float4(0.f, 0.f, 0.f, 0.f);
            if (r < nvalid) {
                if (gg < 8) {
                    v = *(const float4*)&pw[(size_t)(base + r) * PWN + gg * 4];
                } else {
                    int c = cs[r], n = ns[r];
                    if (gg < 16) v = *(const float4*)&g_t[(size_t)c * RED + (gg - 8) * 4];
                    else if (n != c) v = *(const float4*)&g_t[(size_t)n * RED + (gg - 16) * 4];
                }
            }
            uint16_t h0,l0,h1,l1,h2,l2,h3,l3;
            hilo(v.x,h0,l0); hilo(v.y,h1,l1); hilo(v.z,h2,l2); hilo(v.w,h3,l3);
            uint32_t o = (uint32_t)(r * PX + gg * 4) * 2;
            *(uint2*)(smem + OFF_XH + o) = make_uint2(pk2(h0,h1), pk2(h2,h3));
            *(uint2*)(smem + OFF_XL + o) = make_uint2(pk2(l0,l1), pk2(l2,l3));
        }
        __syncthreads();

        // GEMM1: K = 96
        float acc[2][4][4];
        gemm_strip<6>(xh, xl, w0h, w0l, wrow, wcol, lm, acc);
        __syncthreads();   // X reads complete before H1 overwrite

        // epilogue 1: relu(acc+b0) -> hi/lo split -> H1 planes
#pragma unroll
        for (int m = 0; m < 2; m++) {
            const int r0 = wrow + m * 16 + g;
#pragma unroll
            for (int n = 0; n < 4; n++) {
                const int col = wcol + n * 8 + t * 2;
                const float bx = b0s[col], by = b0s[col + 1];
                float v0 = fmaxf(acc[m][n][0] + bx, 0.f);
                float v1 = fmaxf(acc[m][n][1] + by, 0.f);
                float v2 = fmaxf(acc[m][n][2] + bx, 0.f);
                float v3 = fmaxf(acc[m][n][3] + by, 0.f);
                uint16_t h0,l0,h1,l1,h2,l2,h3,l3;
                hilo(v0,h0,l0); hilo(v1,h1,l1); hilo(v2,h2,l2); hilo(v3,h3,l3);
                uint32_t o0 = (uint32_t)(r0 * PX + col) * 2;
                uint32_t o1 = (uint32_t)((r0 + 8) * PX + col) * 2;
                *(uint32_t*)(smem + OFF_XH + o0) = pk2(h0, h1);
                *(uint32_t*)(smem + OFF_XL + o0) = pk2(l0, l1);
                *(uint32_t*)(smem + OFF_XH + o1) = pk2(h2, h3);
                *(uint32_t*)(smem + OFF_XL + o1) = pk2(l2, l3);
            }
        }
        __syncthreads();

        // GEMM2: K = 128
        gemm_strip<8>(xh, xl, w1h, w1l, wrow, wcol, lm, acc);

        // epilogue 2: relu(acc+b1) -> scatter atomicMax (values >= 0)
#pragma unroll
        for (int m = 0; m < 2; m++) {
            const int r0 = wrow + m * 16 + g;
            const int e0 = cs[r0], e1 = cs[r0 + 8];
#pragma unroll
            for (int n = 0; n < 4; n++) {
                const int col = wcol + n * 8 + t * 2;
                const float bx = b1s[col], by = b1s[col + 1];
                if (e0 >= 0) {
                    float v0 = acc[m][n][0] + bx;
                    float v1 = acc[m][n][1] + by;
                    float* dst = &g_tmp[(size_t)e0 * PAIR + col];
                    if (v0 > 0.f) atomicMax((int*)&dst[0], __float_as_int(v0));
                    if (v1 > 0.f) atomicMax((int*)&dst[1], __float_as_int(v1));
                }
                if (e1 >= 0) {
                    float v2 = acc[m][n][2] + bx;
                    float v3 = acc[m][n][3] + by;
                    float* dst = &g_tmp[(size_t)e1 * PAIR + col];
                    if (v2 > 0.f) atomicMax((int*)&dst[0], __float_as_int(v2));
                    if (v3 > 0.f) atomicMax((int*)&dst[1], __float_as_int(v3));
                }
            }
        }
    }
}

// ---------------------------------------------------------------------------
// Kernel 3: node MLP, 64-node tiles (grid ~157), 256 threads
// ---------------------------------------------------------------------------
#define NTS 64
#define ACT_LD 132
#define NODE_SMEM_BYTES ((NTS*ACT_LD + PAIR*PAIR) * 4)

__global__ __launch_bounds__(TPB, 1)
void node_kernel(const float* __restrict__ infeats,
                 const float* __restrict__ Wa, const float* __restrict__ ba,
                 const float* __restrict__ Wb, const float* __restrict__ bb_,
                 const float* __restrict__ W2, const float* __restrict__ b2,
                 float* __restrict__ out, int N) {
    extern __shared__ float smemf[];
    float* acts = smemf;                 // 64 x 132
    float* Ws   = smemf + NTS * ACT_LD;  // 128 x 128

    const int tid = threadIdx.x;
    const int base = blockIdx.x * NTS;
    const int nvalid = min(NTS, N - base);

    for (int idx = tid; idx < NTS * (PAIR / 4); idx += TPB) {
        int node = idx >> 5, k = (idx & 31) * 4;
        float4 v = make_float4(0.f, 0.f, 0.f, 0.f);
        if (node < nvalid) v = *(const float4*)&g_tmp[(size_t)(base + node) * PAIR + k];
        *(float4*)&acts[node * ACT_LD + k] = v;
    }

    const int tx = tid & 15, ty = tid >> 4;   // ty 0..15
    const int col0 = tx * 8, row0 = ty * 4;

    const float* Wp[3] = {Wa, Wb, W2};
    const float* bp[3] = {ba, bb_, b2};

    for (int layer = 0; layer < 3; layer++) {
        __syncthreads();
        for (int i = tid * 4; i < PAIR * PAIR; i += TPB * 4)
            *(float4*)&Ws[i] = *(const float4*)&Wp[layer][i];
        __syncthreads();

        float acc[4][8];
#pragma unroll
        for (int r = 0; r < 4; r++)
#pragma unroll
            for (int c = 0; c < 8; c++) acc[r][c] = 0.f;

        for (int k = 0; k < PAIR; k += 4) {
            float4 a[4];
#pragma unroll
            for (int r = 0; r < 4; r++)
                a[r] = *(float4*)&acts[(row0 + r) * ACT_LD + k];
#pragma unroll
            for (int kk = 0; kk < 4; kk++) {
                float4 w0 = *(float4*)&Ws[(k + kk) * PAIR + col0];
                float4 w1 = *(float4*)&Ws[(k + kk) * PAIR + col0 + 4];
                float b[8] = {w0.x, w0.y, w0.z, w0.w, w1.x, w1.y, w1.z, w1.w};
#pragma unroll
                for (int r = 0; r < 4; r++) {
                    float av = (kk == 0) ? a[r].x : (kk == 1) ? a[r].y
                             : (kk == 2) ? a[r].z : a[r].w;
#pragma unroll
                    for (int c = 0; c < 8; c++) acc[r][c] += av * b[c];
                }
            }
        }
        __syncthreads();

        float bias[8];
#pragma unroll
        for (int c = 0; c < 8; c++) bias[c] = bp[layer][col0 + c];

        if (layer < 2) {
#pragma unroll
            for (int r = 0; r < 4; r++) {
                float4 v0, v1;
                v0.x = fmaxf(acc[r][0] + bias[0], 0.f);
                v0.y = fmaxf(acc[r][1] + bias[1], 0.f);
                v0.z = fmaxf(acc[r][2] + bias[2], 0.f);
                v0.w = fmaxf(acc[r][3] + bias[3], 0.f);
                v1.x = fmaxf(acc[r][4] + bias[4], 0.f);
                v1.y = fmaxf(acc[r][5] + bias[5], 0.f);
                v1.z = fmaxf(acc[r][6] + bias[6], 0.f);
                v1.w = fmaxf(acc[r][7] + bias[7], 0.f);
                *(float4*)&acts[(row0 + r) * ACT_LD + col0]     = v0;
                *(float4*)&acts[(row0 + r) * ACT_LD + col0 + 4] = v1;
            }
        } else {
#pragma unroll
            for (int r = 0; r < 4; r++) {
                int node = row0 + r;
                if (node < nvalid) {
                    const float* inrow = &infeats[(size_t)(base + node) * SC + col0];
                    float* orow = &out[(size_t)(base + node) * SC + col0];
                    float4 i0 = *(const float4*)&inrow[0];
                    float4 i1 = *(const float4*)&inrow[4];
                    float4 v0, v1;
                    v0.x = fmaxf(acc[r][0] + bias[0] + i0.x, 0.f);
                    v0.y = fmaxf(acc[r][1] + bias[1] + i0.y, 0.f);
                    v0.z = fmaxf(acc[r][2] + bias[2] + i0.z, 0.f);
                    v0.w = fmaxf(acc[r][3] + bias[3] + i0.w, 0.f);
                    v1.x = fmaxf(acc[r][4] + bias[4] + i1.x, 0.f);
                    v1.y = fmaxf(acc[r][5] + bias[5] + i1.y, 0.f);
                    v1.z = fmaxf(acc[r][6] + bias[6] + i1.z, 0.f);
                    v1.w = fmaxf(acc[r][7] + bias[7] + i1.w, 0.f);
                    *(float4*)&orow[0] = v0;
                    *(float4*)&orow[4] = v1;
                }
            }
        }
    }
}

// ---------------------------------------------------------------------------
extern "C" void kernel_launch(void* const* d_in, const int* in_sizes, int n_in,
                              void* d_out, int out_size) {
    const float* infeats = (const float*)d_in[0];
    const float* pw      = (const float*)d_in[1];
    const int*   c_idxs  = (const int*)d_in[2];
    const int*   n_idxs  = (const int*)d_in[3];
    const float* W_rd  = (const float*)d_in[5];
    const float* b_rd  = (const float*)d_in[6];
    const float* W_pw0 = (const float*)d_in[7];
    const float* b_pw0 = (const float*)d_in[8];
    const float* W_pw1 = (const float*)d_in[9];
    const float* b_pw1 = (const float*)d_in[10];
    const float* W_f1a = (const float*)d_in[11];
    const float* b_f1a = (const float*)d_in[12];
    const float* W_f1b = (const float*)d_in[13];
    const float* b_f1b = (const float*)d_in[14];
    const float* W_f2  = (const float*)d_in[15];
    const float* b_f2  = (const float*)d_in[16];
    float* out = (float*)d_out;

    const int N = in_sizes[0] / SC;
    const int E = in_sizes[1] / PWN;

    cudaFuncSetAttribute(edge_kernel, cudaFuncAttributeMaxDynamicSharedMemorySize,
                         EDGE_SMEM_BYTES);
    cudaFuncSetAttribute(node_kernel, cudaFuncAttributeMaxDynamicSharedMemorySize,
                         NODE_SMEM_BYTES);

    const int tot = N * PAIR;
    clear_accum_kernel<<<(tot + 255) / 256, 256>>>(tot);

    reduce_kernel<<<(N + 7) / 8, TPB>>>(infeats, W_rd, b_rd, N);

    const int ntiles = (E + TS - 1) / TS;
    const int grid = ntiles < 148 ? ntiles : 148;
    edge_kernel<<<grid, ETPB, EDGE_SMEM_BYTES>>>(pw, c_idxs, n_idxs,
                                                 W_pw0, b_pw0, W_pw1, b_pw1,
                                                 E, ntiles);

    node_kernel<<<(N + NTS - 1) / NTS, TPB, NODE_SMEM_BYTES>>>(
        infeats, W_f1a, b_f1a, W_f1b, b_f1b, W_f2, b_f2, out, N);
}

// round 9
// speedup vs baseline: 2.3294x; 1.1929x over previous
#include <cuda_runtime.h>
#include <cuda_fp16.h>
#include <cstdint>

// Fused edge-MLP graph network, fp16 hi/lo 2-pass tensor-core path. v9.
#define N_MAX 16384
#define SC    128
#define RED   32
#define PWN   32
#define PAIR  128
#define XDIM  96

#define TPB  256
#define ETPB 512
#define TS   128
#define PX   136     // fp16 element pitch of activation/weight planes

__device__ float g_t[(size_t)N_MAX * RED];
__device__ float g_tmp[(size_t)N_MAX * PAIR];

// ---------------------------------------------------------------------------
// helpers
// ---------------------------------------------------------------------------
__device__ __forceinline__ uint32_t smem_addr32(const void* p) {
    uint32_t a;
    asm("{ .reg .u64 t; cvta.to.shared.u64 t, %1; cvt.u32.u64 %0, t; }" : "=r"(a) : "l"(p));
    return a;
}
__device__ __forceinline__ void ldsm4(uint32_t& r0, uint32_t& r1, uint32_t& r2,
                                      uint32_t& r3, uint32_t addr) {
    asm volatile("ldmatrix.sync.aligned.m8n8.x4.shared.b16 {%0,%1,%2,%3}, [%4];"
                 : "=r"(r0), "=r"(r1), "=r"(r2), "=r"(r3) : "r"(addr));
}
__device__ __forceinline__ void hmma_f16(float* c, const uint32_t* a, const uint32_t* b) {
    asm volatile(
        "mma.sync.aligned.m16n8k16.row.col.f32.f16.f16.f32 "
        "{%0,%1,%2,%3}, {%4,%5,%6,%7}, {%8,%9}, {%0,%1,%2,%3};"
        : "+f"(c[0]), "+f"(c[1]), "+f"(c[2]), "+f"(c[3])
        : "r"(a[0]), "r"(a[1]), "r"(a[2]), "r"(a[3]), "r"(b[0]), "r"(b[1]));
}
__device__ __forceinline__ uint16_t f2h(float x) {
    __half h = __float2half_rn(x);
    return *(uint16_t*)&h;
}
__device__ __forceinline__ void hilo_h(float x, uint16_t& h, uint16_t& l) {
    __half hb = __float2half_rn(x);
    __half lb = __float2half_rn(x - __half2float(hb));
    h = *(uint16_t*)&hb;
    l = *(uint16_t*)&lb;
}
__device__ __forceinline__ uint32_t pk2(uint16_t a, uint16_t b) {
    return (uint32_t)a | ((uint32_t)b << 16);
}

// ---------------------------------------------------------------------------
__global__ void clear_accum_kernel(int total) {
    int i = blockIdx.x * blockDim.x + threadIdx.x;
    if (i < total) g_tmp[i] = 0.0f;
}

// ---------------------------------------------------------------------------
// Kernel 1: t = relu(infeats @ W_rd + b_rd)
// ---------------------------------------------------------------------------
__global__ __launch_bounds__(TPB, 1)
void reduce_kernel(const float* __restrict__ infeats,
                   const float* __restrict__ W_rd,
                   const float* __restrict__ b_rd, int N) {
    __shared__ float Ws[SC * RED];
    __shared__ float rows[8 * SC];
    const int tid = threadIdx.x;
    const int base = blockIdx.x * 8;
    for (int i = tid; i < SC * RED; i += TPB) Ws[i] = W_rd[i];
    for (int i = tid; i < 8 * SC; i += TPB) {
        int nl = i >> 7, k = i & 127;
        rows[i] = (base + nl < N) ? infeats[(size_t)(base + nl) * SC + k] : 0.0f;
    }
    __syncthreads();
    const int nl = tid >> 5, r = tid & 31;
    float acc = b_rd[r];
#pragma unroll 8
    for (int i = 0; i < SC; i++) acc += rows[nl * SC + i] * Ws[i * RED + r];
    if (base + nl < N) g_t[(size_t)(base + nl) * RED + r] = fmaxf(acc, 0.0f);
}

// ---------------------------------------------------------------------------
// Kernel 2: fused edge MLP (mma.sync fp16, act 1 plane x weight hi/lo 2-pass)
// + scatter-max. 512 threads / 16 warps; warp strip = 32 rows x 32 cols.
// ---------------------------------------------------------------------------
#define PLANE_B (128 * PX * 2)   // 34816 bytes per fp16 plane
#define OFF_X   0
#define OFF_W0H (OFF_X + PLANE_B)
#define OFF_W0L (OFF_W0H + PLANE_B)
#define OFF_W1H (OFF_W0L + PLANE_B)
#define OFF_W1L (OFF_W1H + PLANE_B)
#define OFF_CS  (OFF_W1L + PLANE_B)
#define OFF_NS  (OFF_CS + 512)
#define OFF_B0  (OFF_NS + 512)
#define OFF_B1  (OFF_B0 + 512)
#define EDGE_SMEM_BYTES (OFF_B1 + 512)

struct LaneMap { int a_row, a_col, b_row, b_col; };

// 2-pass GEMM strip: acc += Ah * (Wh + Wl)
template <int KS>
__device__ __forceinline__ void gemm_strip(uint32_t x,
                                           uint32_t wh, uint32_t wl,
                                           int wrow, int wcol, LaneMap lm,
                                           float acc[2][4][4]) {
#pragma unroll
    for (int m = 0; m < 2; m++)
#pragma unroll
        for (int n = 0; n < 4; n++)
#pragma unroll
            for (int i = 0; i < 4; i++) acc[m][n][i] = 0.f;

#pragma unroll 2
    for (int ks = 0; ks < KS; ks++) {
        const int k0 = ks * 16;
        uint32_t A[2][4];
#pragma unroll
        for (int m = 0; m < 2; m++) {
            uint32_t off = (uint32_t)((wrow + m * 16 + lm.a_row) * PX + k0 + lm.a_col) * 2;
            ldsm4(A[m][0], A[m][1], A[m][2], A[m][3], x + off);
        }
        uint32_t Bh[4][2], Bl[4][2];
#pragma unroll
        for (int nn = 0; nn < 2; nn++) {
            uint32_t off = (uint32_t)((wcol + nn * 16 + lm.b_row) * PX + k0 + lm.b_col) * 2;
            uint32_t r0, r1, r2, r3;
            ldsm4(r0, r1, r2, r3, wh + off);
            Bh[nn * 2][0] = r0;     Bh[nn * 2][1] = r1;
            Bh[nn * 2 + 1][0] = r2; Bh[nn * 2 + 1][1] = r3;
            ldsm4(r0, r1, r2, r3, wl + off);
            Bl[nn * 2][0] = r0;     Bl[nn * 2][1] = r1;
            Bl[nn * 2 + 1][0] = r2; Bl[nn * 2 + 1][1] = r3;
        }
#pragma unroll
        for (int m = 0; m < 2; m++)
#pragma unroll
            for (int n = 0; n < 4; n++) {
                hmma_f16(acc[m][n], A[m], Bh[n]);
                hmma_f16(acc[m][n], A[m], Bl[n]);
            }
    }
}

__global__ __launch_bounds__(ETPB, 1)
void edge_kernel(const float* __restrict__ pw,
                 const int* __restrict__ c_idx,
                 const int* __restrict__ n_idx,
                 const float* __restrict__ W0, const float* __restrict__ b0,
                 const float* __restrict__ W1, const float* __restrict__ b1,
                 int E, int ntiles) {
    extern __shared__ char smem[];
    const uint32_t sb  = smem_addr32(smem);
    const uint32_t x   = sb + OFF_X;
    const uint32_t w0h = sb + OFF_W0H, w0l = sb + OFF_W0L;
    const uint32_t w1h = sb + OFF_W1H, w1l = sb + OFF_W1L;
    int*   cs  = (int*)(smem + OFF_CS);
    int*   ns  = (int*)(smem + OFF_NS);
    float* b0s = (float*)(smem + OFF_B0);
    float* b1s = (float*)(smem + OFF_B1);

    const int tid = threadIdx.x;
    const int wid = tid >> 5, lid = tid & 31;
    const int wrow = (wid & 3) * 32;
    const int wcol = (wid >> 2) * 32;
    const int g = lid >> 2, t = lid & 3;

    LaneMap lm;
    lm.a_row = (lid & 7) + ((lid >> 3) & 1) * 8;
    lm.a_col = ((lid >> 4) & 1) * 8;
    lm.b_row = (lid & 7) + ((lid >> 4) & 1) * 8;
    lm.b_col = ((lid >> 3) & 1) * 8;

    // weights: transpose W[k][j] -> planes[j][k], fp16 hi/lo split
    for (int idx = tid; idx < XDIM * PAIR; idx += ETPB) {
        int k = idx >> 7, j = idx & 127;
        uint16_t h, l; hilo_h(W0[idx], h, l);
        uint32_t o = (uint32_t)(j * PX + k) * 2;
        *(uint16_t*)(smem + OFF_W0H + o) = h;
        *(uint16_t*)(smem + OFF_W0L + o) = l;
    }
    for (int idx = tid; idx < PAIR * PAIR; idx += ETPB) {
        int k = idx >> 7, j = idx & 127;
        uint16_t h, l; hilo_h(W1[idx], h, l);
        uint32_t o = (uint32_t)(j * PX + k) * 2;
        *(uint16_t*)(smem + OFF_W1H + o) = h;
        *(uint16_t*)(smem + OFF_W1L + o) = l;
    }
    if (tid < PAIR) { b0s[tid] = b0[tid]; b1s[tid] = b1[tid]; }

    for (int tile = blockIdx.x; tile < ntiles; tile += gridDim.x) {
        const int base = tile * TS;
        const int nvalid = min(TS, E - base);
        __syncthreads();   // previous tile fully consumed
        if (tid < TS) {
            bool ok = tid < nvalid;
            cs[tid] = ok ? c_idx[base + tid] : -1;
            ns[tid] = ok ? n_idx[base + tid] : -1;
        }
        __syncthreads();

        // gather X rows (edges), cols 0..95, fp16 single plane
        for (int idx = tid; idx < TS * 24; idx += ETPB) {
            int r = idx / 24, gg = idx - r * 24;
            float4 v = make_float4(0.f, 0.f, 0.f, 0.f);
            if (r < nvalid) {
                if (gg < 8) {
                    v = *(const float4*)&pw[(size_t)(base + r) * PWN + gg * 4];
                } else {
                    int c = cs[r], n = ns[r];
                    if (gg < 16) v = *(const float4*)&g_t[(size_t)c * RED + (gg - 8) * 4];
                    else if (n != c) v = *(const float4*)&g_t[(size_t)n * RED + (gg - 16) * 4];
                }
            }
            uint32_t o = (uint32_t)(r * PX + gg * 4) * 2;
            *(uint2*)(smem + OFF_X + o) =
                make_uint2(pk2(f2h(v.x), f2h(v.y)), pk2(f2h(v.z), f2h(v.w)));
        }
        __syncthreads();

        // GEMM1: K = 96
        float acc[2][4][4];
        gemm_strip<6>(x, w0h, w0l, wrow, wcol, lm, acc);
        __syncthreads();   // X reads complete before H1 overwrite

        // epilogue 1: relu(acc+b0) -> fp16 -> H1 plane (in place of X)
#pragma unroll
        for (int m = 0; m < 2; m++) {
            const int r0 = wrow + m * 16 + g;
#pragma unroll
            for (int n = 0; n < 4; n++) {
                const int col = wcol + n * 8 + t * 2;
                const float bx = b0s[col], by = b0s[col + 1];
                float v0 = fmaxf(acc[m][n][0] + bx, 0.f);
                float v1 = fmaxf(acc[m][n][1] + by, 0.f);
                float v2 = fmaxf(acc[m][n][2] + bx, 0.f);
                float v3 = fmaxf(acc[m][n][3] + by, 0.f);
                uint32_t o0 = (uint32_t)(r0 * PX + col) * 2;
                uint32_t o1 = (uint32_t)((r0 + 8) * PX + col) * 2;
                *(uint32_t*)(smem + OFF_X + o0) = pk2(f2h(v0), f2h(v1));
                *(uint32_t*)(smem + OFF_X + o1) = pk2(f2h(v2), f2h(v3));
            }
        }
        __syncthreads();

        // GEMM2: K = 128
        gemm_strip<8>(x, w1h, w1l, wrow, wcol, lm, acc);

        // epilogue 2: relu(acc+b1) -> scatter atomicMax (values >= 0)
#pragma unroll
        for (int m = 0; m < 2; m++) {
            const int r0 = wrow + m * 16 + g;
            const int e0 = cs[r0], e1 = cs[r0 + 8];
#pragma unroll
            for (int n = 0; n < 4; n++) {
                const int col = wcol + n * 8 + t * 2;
                const float bx = b1s[col], by = b1s[col + 1];
                if (e0 >= 0) {
                    float v0 = acc[m][n][0] + bx;
                    float v1 = acc[m][n][1] + by;
                    float* dst = &g_tmp[(size_t)e0 * PAIR + col];
                    if (v0 > 0.f) atomicMax((int*)&dst[0], __float_as_int(v0));
                    if (v1 > 0.f) atomicMax((int*)&dst[1], __float_as_int(v1));
                }
                if (e1 >= 0) {
                    float v2 = acc[m][n][2] + bx;
                    float v3 = acc[m][n][3] + by;
                    float* dst = &g_tmp[(size_t)e1 * PAIR + col];
                    if (v2 > 0.f) atomicMax((int*)&dst[0], __float_as_int(v2));
                    if (v3 > 0.f) atomicMax((int*)&dst[1], __float_as_int(v3));
                }
            }
        }
    }
}

// ---------------------------------------------------------------------------
// Kernel 3: node MLP, 64-node tiles; ALL 3 weight layers preloaded in smem.
// ---------------------------------------------------------------------------
#define NTS 64
#define ACT_LD 132
#define NODE_SMEM_BYTES ((NTS*ACT_LD + 3*PAIR*PAIR) * 4)   // 230400 B

__global__ __launch_bounds__(TPB, 1)
void node_kernel(const float* __restrict__ infeats,
                 const float* __restrict__ Wa, const float* __restrict__ ba,
                 const float* __restrict__ Wb, const float* __restrict__ bb_,
                 const float* __restrict__ W2, const float* __restrict__ b2,
                 float* __restrict__ out, int N) {
    extern __shared__ float smemf[];
    float* acts = smemf;                  // 64 x 132
    float* Wall = smemf + NTS * ACT_LD;   // 3 x 128 x 128

    const int tid = threadIdx.x;
    const int base = blockIdx.x * NTS;
    const int nvalid = min(NTS, N - base);

    // preload all three weight matrices + activations concurrently
    const float* Wp[3] = {Wa, Wb, W2};
    for (int lyr = 0; lyr < 3; lyr++) {
        float* dst = Wall + lyr * PAIR * PAIR;
        const float* src = Wp[lyr];
        for (int i = tid * 4; i < PAIR * PAIR; i += TPB * 4)
            *(float4*)&dst[i] = *(const float4*)&src[i];
    }
    for (int idx = tid; idx < NTS * (PAIR / 4); idx += TPB) {
        int node = idx >> 5, k = (idx & 31) * 4;
        float4 v = make_float4(0.f, 0.f, 0.f, 0.f);
        if (node < nvalid) v = *(const float4*)&g_tmp[(size_t)(base + node) * PAIR + k];
        *(float4*)&acts[node * ACT_LD + k] = v;
    }
    __syncthreads();

    const int tx = tid & 15, ty = tid >> 4;   // ty 0..15
    const int col0 = tx * 8, row0 = ty * 4;

    const float* bp[3] = {ba, bb_, b2};

    for (int layer = 0; layer < 3; layer++) {
        const float* Ws = Wall + layer * PAIR * PAIR;

        float acc[4][8];
#pragma unroll
        for (int r = 0; r < 4; r++)
#pragma unroll
            for (int c = 0; c < 8; c++) acc[r][c] = 0.f;

        for (int k = 0; k < PAIR; k += 4) {
            float4 a[4];
#pragma unroll
            for (int r = 0; r < 4; r++)
                a[r] = *(float4*)&acts[(row0 + r) * ACT_LD + k];
#pragma unroll
            for (int kk = 0; kk < 4; kk++) {
                float4 w0 = *(const float4*)&Ws[(k + kk) * PAIR + col0];
                float4 w1 = *(const float4*)&Ws[(k + kk) * PAIR + col0 + 4];
                float b[8] = {w0.x, w0.y, w0.z, w0.w, w1.x, w1.y, w1.z, w1.w};
#pragma unroll
                for (int r = 0; r < 4; r++) {
                    float av = (kk == 0) ? a[r].x : (kk == 1) ? a[r].y
                             : (kk == 2) ? a[r].z : a[r].w;
#pragma unroll
                    for (int c = 0; c < 8; c++) acc[r][c] += av * b[c];
                }
            }
        }
        __syncthreads();   // acts reads complete

        float bias[8];
#pragma unroll
        for (int c = 0; c < 8; c++) bias[c] = bp[layer][col0 + c];

        if (layer < 2) {
#pragma unroll
            for (int r = 0; r < 4; r++) {
                float4 v0, v1;
                v0.x = fmaxf(acc[r][0] + bias[0], 0.f);
                v0.y = fmaxf(acc[r][1] + bias[1], 0.f);
                v0.z = fmaxf(acc[r][2] + bias[2], 0.f);
                v0.w = fmaxf(acc[r][3] + bias[3], 0.f);
                v1.x = fmaxf(acc[r][4] + bias[4], 0.f);
                v1.y = fmaxf(acc[r][5] + bias[5], 0.f);
                v1.z = fmaxf(acc[r][6] + bias[6], 0.f);
                v1.w = fmaxf(acc[r][7] + bias[7], 0.f);
                *(float4*)&acts[(row0 + r) * ACT_LD + col0]     = v0;
                *(float4*)&acts[(row0 + r) * ACT_LD + col0 + 4] = v1;
            }
            __syncthreads();   // acts writes visible before next layer reads
        } else {
#pragma unroll
            for (int r = 0; r < 4; r++) {
                int node = row0 + r;
                if (node < nvalid) {
                    const float* inrow = &infeats[(size_t)(base + node) * SC + col0];
                    float* orow = &out[(size_t)(base + node) * SC + col0];
                    float4 i0 = *(const float4*)&inrow[0];
                    float4 i1 = *(const float4*)&inrow[4];
                    float4 v0, v1;
                    v0.x = fmaxf(acc[r][0] + bias[0] + i0.x, 0.f);
                    v0.y = fmaxf(acc[r][1] + bias[1] + i0.y, 0.f);
                    v0.z = fmaxf(acc[r][2] + bias[2] + i0.z, 0.f);
                    v0.w = fmaxf(acc[r][3] + bias[3] + i0.w, 0.f);
                    v1.x = fmaxf(acc[r][4] + bias[4] + i1.x, 0.f);
                    v1.y = fmaxf(acc[r][5] + bias[5] + i1.y, 0.f);
                    v1.z = fmaxf(acc[r][6] + bias[6] + i1.z, 0.f);
                    v1.w = fmaxf(acc[r][7] + bias[7] + i1.w, 0.f);
                    *(float4*)&orow[0] = v0;
                    *(float4*)&orow[4] = v1;
                }
            }
        }
    }
}

// ---------------------------------------------------------------------------
extern "C" void kernel_launch(void* const* d_in, const int* in_sizes, int n_in,
                              void* d_out, int out_size) {
    const float* infeats = (const float*)d_in[0];
    const float* pw      = (const float*)d_in[1];
    const int*   c_idxs  = (const int*)d_in[2];
    const int*   n_idxs  = (const int*)d_in[3];
    const float* W_rd  = (const float*)d_in[5];
    const float* b_rd  = (const float*)d_in[6];
    const float* W_pw0 = (const float*)d_in[7];
    const float* b_pw0 = (const float*)d_in[8];
    const float* W_pw1 = (const float*)d_in[9];
    const float* b_pw1 = (const float*)d_in[10];
    const float* W_f1a = (const float*)d_in[11];
    const float* b_f1a = (const float*)d_in[12];
    const float* W_f1b = (const float*)d_in[13];
    const float* b_f1b = (const float*)d_in[14];
    const float* W_f2  = (const float*)d_in[15];
    const float* b_f2  = (const float*)d_in[16];
    float* out = (float*)d_out;

    const int N = in_sizes[0] / SC;
    const int E = in_sizes[1] / PWN;

    cudaFuncSetAttribute(edge_kernel, cudaFuncAttributeMaxDynamicSharedMemorySize,
                         EDGE_SMEM_BYTES);
    cudaFuncSetAttribute(node_kernel, cudaFuncAttributeMaxDynamicSharedMemorySize,
                         NODE_SMEM_BYTES);

    const int tot = N * PAIR;
    clear_accum_kernel<<<(tot + 255) / 256, 256>>>(tot);

    reduce_kernel<<<(N + 7) / 8, TPB>>>(infeats, W_rd, b_rd, N);

    const int ntiles = (E + TS - 1) / TS;
    const int grid = ntiles < 148 ? ntiles : 148;
    edge_kernel<<<grid, ETPB, EDGE_SMEM_BYTES>>>(pw, c_idxs, n_idxs,
                                                 W_pw0, b_pw0, W_pw1, b_pw1,
                                                 E, ntiles);

    node_kernel<<<(N + NTS - 1) / NTS, TPB, NODE_SMEM_BYTES>>>(
        infeats, W_f1a, b_f1a, W_f1b, b_f1b, W_f2, b_f2, out, N);
}